// round 16
// baseline (speedup 1.0000x reference)
#include <cuda_runtime.h>
#include <cuda_bf16.h>
#include <cuda_fp8.h>
#include <cstdint>

// ---------------------------------------------------------------------------
// mLSTM single step, B=8192, V=50257, E=1024, H=2048, O=2
//   x   = emb[inp]
//   m_t = (x@W_mx^T + b_mx) * (h0@W_mh^T + b_mh)            [bf16 HMMA]
//   ct  = tanh(x@W_cx^T + m_t@W_cm^T + b)                   [bf16 HMMA] -> bf16
//   z_o = x@W_ox^T + m_t@W_om^T + b                         [fp8 QMMA] -> bf16
//   f,i = sigmoid(x@W_zx^T + m_t@W_zm^T + b)                [fp8 QMMA]
//   cx  = f*c0 + i*ct ; hx = sigmoid(z_o)*tanh(cx) ; out = hx@W_dec^T + b_dec
// d_out: [ out(B,2) | hx(B,H) | cx(B,H) ]  fp32
//
// r10 structure (best measured: 1907us) + (a) ct stored bf16, (b) off-critical
// weight conversions forked onto a second captured stream, hidden under gemm_mt.
// All GEMMs: BM=128, BN=128 (fi: 2 gates), 512 thr, warp tile 32x32, 3-stage
// cp.async, one __syncthreads per k-tile, 144B row stride. fp8 scales: x*64,
// W*64, m_t*256; x-phase acc*4 at boundary; dequant 2^-14.
// ---------------------------------------------------------------------------

#define B_  8192
#define E_  1024
#define H_  2048
#define MEG (1 << 20)

__device__ __align__(16) __nv_bfloat16 g_xb [(size_t)B_ * E_];   // bf16 x
__device__ __align__(16) __nv_bfloat16 g_h0b[(size_t)B_ * H_];   // bf16 h0
__device__ __align__(16) __nv_bfloat16 g_mtb[(size_t)B_ * H_];   // bf16 m_t
__device__ __align__(16) __nv_bfloat16 g_zo [(size_t)B_ * H_];   // bf16 z_o pre-act
__device__ __align__(16) __nv_bfloat16 g_ct [(size_t)B_ * H_];   // bf16 c~
__device__ __align__(16) __nv_bfloat16 g_wbf[(size_t)12 * MEG];  // bf16 W_mx,W_mh,W_cx,W_cm
__device__ __align__(16) uint8_t       g_x8 [(size_t)B_ * E_];   // fp8 x*64
__device__ __align__(16) uint8_t       g_mt8[(size_t)B_ * H_];   // fp8 m_t*256
__device__ __align__(16) uint8_t       g_w8 [(size_t)18 * MEG];  // fp8 f,i,o W*64

#define OFF_MX 0
#define OFF_MH (2 * MEG)
#define OFF_CX (6 * MEG)
#define OFF_CM (8 * MEG)
#define OFF8_ZX(z) ((size_t)(z) * 6 * MEG)            // z: 0=f 1=i 2=o
#define OFF8_ZM(z) ((size_t)(z) * 6 * MEG + 2 * MEG)

// ---------------------------------------------------------------------------
// helpers
// ---------------------------------------------------------------------------
__device__ __forceinline__ uint32_t smem_u32(const void* p) {
    uint32_t a;
    asm("{ .reg .u64 t; cvta.to.shared.u64 t, %1; cvt.u32.u64 %0, t; }"
        : "=r"(a) : "l"(p));
    return a;
}
__device__ __forceinline__ void cpa16(uint32_t dst, const void* src) {
    asm volatile("cp.async.cg.shared.global [%0], [%1], 16;\n" :: "r"(dst), "l"(src));
}
__device__ __forceinline__ void cp_commit() { asm volatile("cp.async.commit_group;\n" ::); }
template <int N> __device__ __forceinline__ void cp_wait() {
    asm volatile("cp.async.wait_group %0;\n" :: "n"(N));
}
__device__ __forceinline__ void ldsm4(uint32_t& r0, uint32_t& r1, uint32_t& r2,
                                      uint32_t& r3, uint32_t addr) {
    asm volatile("ldmatrix.sync.aligned.m8n8.x4.shared.b16 {%0,%1,%2,%3}, [%4];"
                 : "=r"(r0), "=r"(r1), "=r"(r2), "=r"(r3) : "r"(addr));
}
__device__ __forceinline__ void mma16816(float c[4], const uint32_t a[4], const uint32_t b[2]) {
    asm volatile(
        "mma.sync.aligned.m16n8k16.row.col.f32.bf16.bf16.f32 "
        "{%0,%1,%2,%3}, {%4,%5,%6,%7}, {%8,%9}, {%0,%1,%2,%3};\n"
        : "+f"(c[0]), "+f"(c[1]), "+f"(c[2]), "+f"(c[3])
        : "r"(a[0]), "r"(a[1]), "r"(a[2]), "r"(a[3]), "r"(b[0]), "r"(b[1]));
}
__device__ __forceinline__ void mma_fp8(float c[4], const uint32_t a[4], const uint32_t b[2]) {
    asm volatile(
        "mma.sync.aligned.m16n8k32.row.col.f32.e4m3.e4m3.f32 "
        "{%0,%1,%2,%3}, {%4,%5,%6,%7}, {%8,%9}, {%0,%1,%2,%3};\n"
        : "+f"(c[0]), "+f"(c[1]), "+f"(c[2]), "+f"(c[3])
        : "r"(a[0]), "r"(a[1]), "r"(a[2]), "r"(a[3]), "r"(b[0]), "r"(b[1]));
}
__device__ __forceinline__ uint16_t fp8pair(float v0, float v1) {
    uint16_t r;
    asm("cvt.rn.satfinite.e4m3x2.f32 %0, %1, %2;" : "=h"(r) : "f"(v1), "f"(v0));
    return r;
}
__device__ __forceinline__ float sigf(float v)   { return 1.f / (1.f + __expf(-v)); }
__device__ __forceinline__ float tanhf_(float v) { return fmaf(2.f, 1.f / (1.f + __expf(-2.f * v)), -1.f); }

// ---------------------------------------------------------------------------
// conversions + gather
// ---------------------------------------------------------------------------
struct Cvt3 { const float* s[3]; __nv_bfloat16* d[3]; int n4[3]; };

__global__ void cvt_bf16_3(Cvt3 a) {
    const int seg = blockIdx.y;
    const float4* __restrict__ s = (const float4*)a.s[seg];
    uint2* __restrict__ d = (uint2*)a.d[seg];
    const int n4 = a.n4[seg];
    for (int i = blockIdx.x * blockDim.x + threadIdx.x; i < n4;
         i += gridDim.x * blockDim.x) {
        float4 v = s[i];
        __nv_bfloat162 lo = __float22bfloat162_rn(make_float2(v.x, v.y));
        __nv_bfloat162 hi = __float22bfloat162_rn(make_float2(v.z, v.w));
        uint2 o; o.x = *(unsigned*)&lo; o.y = *(unsigned*)&hi;
        d[i] = o;
    }
}

struct Cvt2 { const float* s[2]; __nv_bfloat16* d[2]; int n4[2]; };

__global__ void cvt_bf16_2(Cvt2 a) {
    const int seg = blockIdx.y;
    const float4* __restrict__ s = (const float4*)a.s[seg];
    uint2* __restrict__ d = (uint2*)a.d[seg];
    const int n4 = a.n4[seg];
    for (int i = blockIdx.x * blockDim.x + threadIdx.x; i < n4;
         i += gridDim.x * blockDim.x) {
        float4 v = s[i];
        __nv_bfloat162 lo = __float22bfloat162_rn(make_float2(v.x, v.y));
        __nv_bfloat162 hi = __float22bfloat162_rn(make_float2(v.z, v.w));
        uint2 o; o.x = *(unsigned*)&lo; o.y = *(unsigned*)&hi;
        d[i] = o;
    }
}

struct Cvt6 { const float* s[6]; uint8_t* d[6]; int n4[6]; };

__global__ void cvt_fp8_6(Cvt6 a) {
    const int seg = blockIdx.y;
    const float4* __restrict__ s = (const float4*)a.s[seg];
    uint32_t* __restrict__ d = (uint32_t*)a.d[seg];
    const int n4 = a.n4[seg];
    for (int i = blockIdx.x * blockDim.x + threadIdx.x; i < n4;
         i += gridDim.x * blockDim.x) {
        float4 v = s[i];
        uint32_t lo = fp8pair(v.x * 64.f, v.y * 64.f);
        uint32_t hi = fp8pair(v.z * 64.f, v.w * 64.f);
        d[i] = lo | (hi << 16);
    }
}

__global__ void gather_x(const int* __restrict__ inp, const float* __restrict__ emb) {
    const int b = blockIdx.x;
    const int v = inp[b];
    float4 t = ((const float4*)(emb + (size_t)v * E_))[threadIdx.x];
    __nv_bfloat162 lo = __float22bfloat162_rn(make_float2(t.x, t.y));
    __nv_bfloat162 hi = __float22bfloat162_rn(make_float2(t.z, t.w));
    uint2 o; o.x = *(unsigned*)&lo; o.y = *(unsigned*)&hi;
    ((uint2*)(g_xb + (size_t)b * E_))[threadIdx.x] = o;
    uint32_t l8 = fp8pair(t.x * 64.f, t.y * 64.f);
    uint32_t h8 = fp8pair(t.z * 64.f, t.w * 64.f);
    ((uint32_t*)(g_x8 + (size_t)b * E_))[threadIdx.x] = l8 | (h8 << 16);
}

// ---------------------------------------------------------------------------
// bf16 GEMMs: BM=128, BN=128, BK=64; rows 144 B; 3 stages; one sync/iter
// ---------------------------------------------------------------------------
#define BST    18432                 // 128 rows * 144 B
#define STG_B  (2 * BST)
#define BF_SMEM (3 * STG_B + 1024)
#define NTB_X  16
#define NTB    48

// m_t: dual accumulation -> bf16 + fp8*256
__global__ __launch_bounds__(512, 1)
void gemm_mt(const float* __restrict__ b_mx, const float* __restrict__ b_mh) {
    extern __shared__ __align__(16) char sm[];
    const uint32_t smb = smem_u32(sm);
    float* bs = (float*)(sm + 3 * STG_B);

    const int m0 = blockIdx.y * 128;
    const int n0 = blockIdx.x * 128;
    const int tid = threadIdx.x, lane = tid & 31, warp = tid >> 5;
    const int wm = warp & 3, wn = warp >> 2;
    const int g = lane >> 2, ti = lane & 3;
    const int l16 = lane & 15, kh = lane >> 4;

    if (tid < 128) {
        bs[tid]       = b_mx[n0 + tid];
        bs[128 + tid] = b_mh[n0 + tid];
    }

    float ax[2][4][4], ah[2][4][4];
#pragma unroll
    for (int mt = 0; mt < 2; mt++)
#pragma unroll
        for (int q = 0; q < 4; q++)
#pragma unroll
            for (int j = 0; j < 4; j++) { ax[mt][q][j] = 0.f; ah[mt][q][j] = 0.f; }

    auto issue = [&](int t, int s) {
        const __nv_bfloat16 *Ab, *Wb; int ld; int tt = t;
        if (t < NTB_X) { Ab = g_xb;  Wb = g_wbf + OFF_MX; ld = E_; }
        else           { Ab = g_h0b; Wb = g_wbf + OFF_MH; ld = H_; tt = t - NTB_X; }
        const int k0 = tt * 64;
        const uint32_t base = smb + s * STG_B;
#pragma unroll
        for (int i = 0; i < 2; i++) {
            int lin = tid + i * 512, r = lin >> 3, c = lin & 7;
            cpa16(base + r * 144 + c * 16,       Ab + (size_t)(m0 + r) * ld + k0 + c * 8);
            cpa16(base + BST + r * 144 + c * 16, Wb + (size_t)(n0 + r) * ld + k0 + c * 8);
        }
        cp_commit();
    };

    issue(0, 0); issue(1, 1);
    for (int t = 0; t < NTB; t++) {
        if (t + 1 < NTB) cp_wait<1>(); else cp_wait<0>();
        __syncthreads();
        if (t + 2 < NTB) issue(t + 2, (t + 2) % 3);
        const uint32_t base = smb + (t % 3) * STG_B;
        const bool px = (t < NTB_X);
#pragma unroll
        for (int ks = 0; ks < 4; ks++) {
            const int kb = ks * 32;
            uint32_t af[2][4];
#pragma unroll
            for (int mt = 0; mt < 2; mt++)
                ldsm4(af[mt][0], af[mt][1], af[mt][2], af[mt][3],
                      base + (wm * 32 + mt * 16 + l16) * 144 + kb + kh * 16);
#pragma unroll
            for (int nt = 0; nt < 2; nt++) {
                uint32_t r0, r1, r2, r3;
                ldsm4(r0, r1, r2, r3,
                      base + BST + (wn * 32 + nt * 16 + l16) * 144 + kb + kh * 16);
                uint32_t b0[2] = {r0, r2}, b1[2] = {r1, r3};
                if (px) {
#pragma unroll
                    for (int mt = 0; mt < 2; mt++) {
                        mma16816(ax[mt][nt * 2],     af[mt], b0);
                        mma16816(ax[mt][nt * 2 + 1], af[mt], b1);
                    }
                } else {
#pragma unroll
                    for (int mt = 0; mt < 2; mt++) {
                        mma16816(ah[mt][nt * 2],     af[mt], b0);
                        mma16816(ah[mt][nt * 2 + 1], af[mt], b1);
                    }
                }
            }
        }
    }

#pragma unroll
    for (int mt = 0; mt < 2; mt++)
#pragma unroll
        for (int q = 0; q < 4; q++) {
            const int nl = wn * 32 + q * 8 + ti * 2;
            const int n = n0 + nl;
#pragma unroll
            for (int h = 0; h < 2; h++) {
                const int m = m0 + wm * 32 + mt * 16 + g + h * 8;
                float v0 = (ax[mt][q][h * 2 + 0] + bs[nl + 0]) *
                           (ah[mt][q][h * 2 + 0] + bs[128 + nl + 0]);
                float v1 = (ax[mt][q][h * 2 + 1] + bs[nl + 1]) *
                           (ah[mt][q][h * 2 + 1] + bs[128 + nl + 1]);
                __nv_bfloat162 p = __float22bfloat162_rn(make_float2(v0, v1));
                *(unsigned*)(g_mtb + (size_t)m * H_ + n) = *(unsigned*)&p;
                *(uint16_t*)(g_mt8 + (size_t)m * H_ + n) =
                    fp8pair(v0 * 256.f, v1 * 256.f);
            }
        }
}

// c-gate: ct = tanh(x@Wcx + m_t@Wcm + b) -> bf16
__global__ __launch_bounds__(512, 1)
void gemm_c(const float* __restrict__ bcx, const float* __restrict__ bcm) {
    extern __shared__ __align__(16) char sm[];
    const uint32_t smb = smem_u32(sm);
    float* bs = (float*)(sm + 3 * STG_B);

    const int m0 = blockIdx.y * 128;
    const int n0 = blockIdx.x * 128;
    const int tid = threadIdx.x, lane = tid & 31, warp = tid >> 5;
    const int wm = warp & 3, wn = warp >> 2;
    const int g = lane >> 2, ti = lane & 3;
    const int l16 = lane & 15, kh = lane >> 4;

    if (tid < 128) bs[tid] = bcx[n0 + tid] + bcm[n0 + tid];

    float acc[2][4][4];
#pragma unroll
    for (int mt = 0; mt < 2; mt++)
#pragma unroll
        for (int q = 0; q < 4; q++)
#pragma unroll
            for (int j = 0; j < 4; j++) acc[mt][q][j] = 0.f;

    auto issue = [&](int t, int s) {
        const __nv_bfloat16 *Ab, *Wb; int ld; int tt = t;
        if (t < NTB_X) { Ab = g_xb;  Wb = g_wbf + OFF_CX; ld = E_; }
        else           { Ab = g_mtb; Wb = g_wbf + OFF_CM; ld = H_; tt = t - NTB_X; }
        const int k0 = tt * 64;
        const uint32_t base = smb + s * STG_B;
#pragma unroll
        for (int i = 0; i < 2; i++) {
            int lin = tid + i * 512, r = lin >> 3, c = lin & 7;
            cpa16(base + r * 144 + c * 16,       Ab + (size_t)(m0 + r) * ld + k0 + c * 8);
            cpa16(base + BST + r * 144 + c * 16, Wb + (size_t)(n0 + r) * ld + k0 + c * 8);
        }
        cp_commit();
    };

    issue(0, 0); issue(1, 1);
    for (int t = 0; t < NTB; t++) {
        if (t + 1 < NTB) cp_wait<1>(); else cp_wait<0>();
        __syncthreads();
        if (t + 2 < NTB) issue(t + 2, (t + 2) % 3);
        const uint32_t base = smb + (t % 3) * STG_B;
#pragma unroll
        for (int ks = 0; ks < 4; ks++) {
            const int kb = ks * 32;
            uint32_t af[2][4];
#pragma unroll
            for (int mt = 0; mt < 2; mt++)
                ldsm4(af[mt][0], af[mt][1], af[mt][2], af[mt][3],
                      base + (wm * 32 + mt * 16 + l16) * 144 + kb + kh * 16);
#pragma unroll
            for (int nt = 0; nt < 2; nt++) {
                uint32_t r0, r1, r2, r3;
                ldsm4(r0, r1, r2, r3,
                      base + BST + (wn * 32 + nt * 16 + l16) * 144 + kb + kh * 16);
                uint32_t b0[2] = {r0, r2}, b1[2] = {r1, r3};
#pragma unroll
                for (int mt = 0; mt < 2; mt++) {
                    mma16816(acc[mt][nt * 2],     af[mt], b0);
                    mma16816(acc[mt][nt * 2 + 1], af[mt], b1);
                }
            }
        }
    }

#pragma unroll
    for (int mt = 0; mt < 2; mt++)
#pragma unroll
        for (int q = 0; q < 4; q++) {
            const int nl = wn * 32 + q * 8 + ti * 2;
            const int n = n0 + nl;
#pragma unroll
            for (int h = 0; h < 2; h++) {
                const int m = m0 + wm * 32 + mt * 16 + g + h * 8;
                float v0 = tanhf_(acc[mt][q][h * 2 + 0] + bs[nl + 0]);
                float v1 = tanhf_(acc[mt][q][h * 2 + 1] + bs[nl + 1]);
                __nv_bfloat162 p = __float22bfloat162_rn(make_float2(v0, v1));
                *(unsigned*)(g_ct + (size_t)m * H_ + n) = *(unsigned*)&p;
            }
        }
}

// ---------------------------------------------------------------------------
// fp8 GEMMs: BM=128, BN=128, BK=128 B; rows 144 B; 3 stages; one sync/iter
// ---------------------------------------------------------------------------
#define F8_NT  24
#define F8_NX  8
#define DQ_    (1.f / 16384.f)
#define O_STG  (2 * BST)
#define O_SMEM (3 * O_STG + 1024)

// o-gate: z_o = x@Wox + m_t@Wom + b  -> bf16 pre-act
__global__ __launch_bounds__(512, 1)
void gemm_o(const float* __restrict__ box_, const float* __restrict__ bom) {
    extern __shared__ __align__(16) char sm[];
    const uint32_t smb = smem_u32(sm);
    float* bs = (float*)(sm + 3 * O_STG);

    const int m0 = blockIdx.y * 128;
    const int n0 = blockIdx.x * 128;
    const int tid = threadIdx.x, lane = tid & 31, warp = tid >> 5;
    const int wm = warp & 3, wn = warp >> 2;
    const int g = lane >> 2, ti = lane & 3;
    const int l16 = lane & 15, kh = lane >> 4;

    if (tid < 128) bs[tid] = box_[n0 + tid] + bom[n0 + tid];

    float acc[2][4][4];
#pragma unroll
    for (int mt = 0; mt < 2; mt++)
#pragma unroll
        for (int q = 0; q < 4; q++)
#pragma unroll
            for (int j = 0; j < 4; j++) acc[mt][q][j] = 0.f;

    auto issue = [&](int t, int s) {
        const bool xph = (t < F8_NX);
        const uint8_t* Ab = xph ? g_x8 : g_mt8;
        const uint8_t* Wb = g_w8 + (xph ? OFF8_ZX(2) : OFF8_ZM(2));
        const int ld = xph ? E_ : H_;
        const int k0 = (xph ? t : t - F8_NX) * 128;
        const uint32_t base = smb + s * O_STG;
#pragma unroll
        for (int i = 0; i < 2; i++) {
            int lin = tid + i * 512, r = lin >> 3, c = lin & 7;
            cpa16(base + r * 144 + c * 16,       Ab + (size_t)(m0 + r) * ld + k0 + c * 16);
            cpa16(base + BST + r * 144 + c * 16, Wb + (size_t)(n0 + r) * ld + k0 + c * 16);
        }
        cp_commit();
    };

    issue(0, 0); issue(1, 1);
    for (int t = 0; t < F8_NT; t++) {
        if (t + 1 < F8_NT) cp_wait<1>(); else cp_wait<0>();
        __syncthreads();
        if (t + 2 < F8_NT) issue(t + 2, (t + 2) % 3);
        if (t == F8_NX) {
#pragma unroll
            for (int mt = 0; mt < 2; mt++)
#pragma unroll
                for (int q = 0; q < 4; q++)
#pragma unroll
                    for (int j = 0; j < 4; j++) acc[mt][q][j] *= 4.f;
        }
        const uint32_t base = smb + (t % 3) * O_STG;
#pragma unroll
        for (int ks = 0; ks < 4; ks++) {
            const int kb = ks * 32;
            uint32_t af[2][4];
#pragma unroll
            for (int mt = 0; mt < 2; mt++)
                ldsm4(af[mt][0], af[mt][1], af[mt][2], af[mt][3],
                      base + (wm * 32 + mt * 16 + l16) * 144 + kb + kh * 16);
#pragma unroll
            for (int nt = 0; nt < 2; nt++) {
                uint32_t r0, r1, r2, r3;
                ldsm4(r0, r1, r2, r3,
                      base + BST + (wn * 32 + nt * 16 + l16) * 144 + kb + kh * 16);
                uint32_t b0[2] = {r0, r2}, b1[2] = {r1, r3};
#pragma unroll
                for (int mt = 0; mt < 2; mt++) {
                    mma_fp8(acc[mt][nt * 2],     af[mt], b0);
                    mma_fp8(acc[mt][nt * 2 + 1], af[mt], b1);
                }
            }
        }
    }

#pragma unroll
    for (int mt = 0; mt < 2; mt++)
#pragma unroll
        for (int q = 0; q < 4; q++) {
            const int nl = wn * 32 + q * 8 + ti * 2;
            const int n = n0 + nl;
#pragma unroll
            for (int h = 0; h < 2; h++) {
                const int m = m0 + wm * 32 + mt * 16 + g + h * 8;
                float v0 = acc[mt][q][h * 2 + 0] * DQ_ + bs[nl + 0];
                float v1 = acc[mt][q][h * 2 + 1] * DQ_ + bs[nl + 1];
                __nv_bfloat162 p = __float22bfloat162_rn(make_float2(v0, v1));
                *(unsigned*)(g_zo + (size_t)m * H_ + n) = *(unsigned*)&p;
            }
        }
}

// f,i gates + final combine: cx/hx into d_out
#define FI_STG (3 * BST)                 // A + 2 B tiles
#define FI_SMEM (3 * FI_STG + 1024)

__global__ __launch_bounds__(512, 1)
void gemm_fi(const float* __restrict__ bfx, const float* __restrict__ bfm,
             const float* __restrict__ bix, const float* __restrict__ bim,
             const float* __restrict__ c0,
             float* __restrict__ hx, float* __restrict__ cx) {
    extern __shared__ __align__(16) char sm[];
    const uint32_t smb = smem_u32(sm);
    float* bs = (float*)(sm + 3 * FI_STG);

    const int m0 = blockIdx.y * 128;
    const int n0 = blockIdx.x * 128;
    const int tid = threadIdx.x, lane = tid & 31, warp = tid >> 5;
    const int wm = warp & 3, wn = warp >> 2;
    const int g = lane >> 2, ti = lane & 3;
    const int l16 = lane & 15, kh = lane >> 4;

    if (tid < 128) {
        const int n = n0 + tid;
        bs[tid]       = bfx[n] + bfm[n];
        bs[128 + tid] = bix[n] + bim[n];
    }

    float acc[2][2][4][4];   // [z][mt][q][j]
#pragma unroll
    for (int z = 0; z < 2; z++)
#pragma unroll
        for (int mt = 0; mt < 2; mt++)
#pragma unroll
            for (int q = 0; q < 4; q++)
#pragma unroll
                for (int j = 0; j < 4; j++) acc[z][mt][q][j] = 0.f;

    auto issue = [&](int t, int s) {
        const bool xph = (t < F8_NX);
        const uint8_t* Ab = xph ? g_x8 : g_mt8;
        const int ld = xph ? E_ : H_;
        const int k0 = (xph ? t : t - F8_NX) * 128;
        const uint32_t base = smb + s * FI_STG;
#pragma unroll
        for (int i = 0; i < 2; i++) {
            int lin = tid + i * 512, r = lin >> 3, c = lin & 7;
            cpa16(base + r * 144 + c * 16, Ab + (size_t)(m0 + r) * ld + k0 + c * 16);
        }
#pragma unroll
        for (int i = 0; i < 4; i++) {
            int lin = tid + i * 512;
            int z = lin >> 10, rr = (lin >> 3) & 127, cc = lin & 7;
            const uint8_t* Wb = g_w8 + (xph ? OFF8_ZX(z) : OFF8_ZM(z));
            cpa16(base + BST + z * BST + rr * 144 + cc * 16,
                  Wb + (size_t)(n0 + rr) * ld + k0 + cc * 16);
        }
        cp_commit();
    };

    issue(0, 0); issue(1, 1);
    for (int t = 0; t < F8_NT; t++) {
        if (t + 1 < F8_NT) cp_wait<1>(); else cp_wait<0>();
        __syncthreads();
        if (t + 2 < F8_NT) issue(t + 2, (t + 2) % 3);
        if (t == F8_NX) {
#pragma unroll
            for (int z = 0; z < 2; z++)
#pragma unroll
                for (int mt = 0; mt < 2; mt++)
#pragma unroll
                    for (int q = 0; q < 4; q++)
#pragma unroll
                        for (int j = 0; j < 4; j++) acc[z][mt][q][j] *= 4.f;
        }
        const uint32_t base = smb + (t % 3) * FI_STG;
#pragma unroll
        for (int ks = 0; ks < 4; ks++) {
            const int kb = ks * 32;
            uint32_t af[2][4];
#pragma unroll
            for (int mt = 0; mt < 2; mt++)
                ldsm4(af[mt][0], af[mt][1], af[mt][2], af[mt][3],
                      base + (wm * 32 + mt * 16 + l16) * 144 + kb + kh * 16);
#pragma unroll
            for (int z = 0; z < 2; z++)
#pragma unroll
                for (int nt = 0; nt < 2; nt++) {
                    uint32_t r0, r1, r2, r3;
                    ldsm4(r0, r1, r2, r3,
                          base + BST + z * BST + (wn * 32 + nt * 16 + l16) * 144 + kb + kh * 16);
                    uint32_t b0[2] = {r0, r2}, b1[2] = {r1, r3};
#pragma unroll
                    for (int mt = 0; mt < 2; mt++) {
                        mma_fp8(acc[z][mt][nt * 2],     af[mt], b0);
                        mma_fp8(acc[z][mt][nt * 2 + 1], af[mt], b1);
                    }
                }
        }
    }

    // epilogue: f,i sigmoids + o (z_o) + ct (bf16) + c0 -> cx, hx
#pragma unroll
    for (int mt = 0; mt < 2; mt++)
#pragma unroll
        for (int q = 0; q < 4; q++) {
            const int nl = wn * 32 + q * 8 + ti * 2;
            const int n = n0 + nl;
#pragma unroll
            for (int h = 0; h < 2; h++) {
                const int m = m0 + wm * 32 + mt * 16 + g + h * 8;
                const size_t off = (size_t)m * H_ + n;
                float2 c0v = *(const float2*)(c0 + off);
                unsigned ctb = *(const unsigned*)(g_ct + off);
                unsigned zob = *(const unsigned*)(g_zo + off);
                __nv_bfloat162 ct2 = *(__nv_bfloat162*)&ctb;
                __nv_bfloat162 zo2 = *(__nv_bfloat162*)&zob;
                float2 hv, cvv;
#pragma unroll
                for (int j = 0; j < 2; j++) {
                    const int e = h * 2 + j;
                    float fg = sigf(acc[0][mt][q][e] * DQ_ + bs[nl + j]);
                    float ig = sigf(acc[1][mt][q][e] * DQ_ + bs[128 + nl + j]);
                    float og = sigf(j ? __bfloat162float(zo2.y)
                                      : __bfloat162float(zo2.x));
                    float ct  = j ? __bfloat162float(ct2.y) : __bfloat162float(ct2.x);
                    float c0e = j ? c0v.y : c0v.x;
                    float cv = fg * c0e + ig * ct;
                    ((float*)&cvv)[j] = cv;
                    ((float*)&hv)[j]  = og * tanhf_(cv);
                }
                *(float2*)(cx + off) = cvv;
                *(float2*)(hx + off) = hv;
            }
        }
}

// ---------------------------------------------------------------------------
// decoder
// ---------------------------------------------------------------------------
__global__ void decoder(const float* __restrict__ hx, const float* __restrict__ Wd,
                        const float* __restrict__ bd, float* __restrict__ out) {
    const int gw = (blockIdx.x * blockDim.x + threadIdx.x) >> 5;
    const int lane = threadIdx.x & 31;
    if (gw >= B_) return;
    const float4* h4 = (const float4*)(hx + (size_t)gw * H_);
    const float4* w0 = (const float4*)(Wd);
    const float4* w1 = (const float4*)(Wd + H_);
    float s0 = 0.f, s1 = 0.f;
    for (int i = lane; i < H_ / 4; i += 32) {
        float4 h = h4[i], a = w0[i], b = w1[i];
        s0 += h.x * a.x + h.y * a.y + h.z * a.z + h.w * a.w;
        s1 += h.x * b.x + h.y * b.y + h.z * b.z + h.w * b.w;
    }
#pragma unroll
    for (int o = 16; o; o >>= 1) {
        s0 += __shfl_xor_sync(0xFFFFFFFFu, s0, o);
        s1 += __shfl_xor_sync(0xFFFFFFFFu, s1, o);
    }
    if (lane == 0) {
        out[(size_t)gw * 2 + 0] = s0 + bd[0];
        out[(size_t)gw * 2 + 1] = s1 + bd[1];
    }
}

// ---------------------------------------------------------------------------
extern "C" void kernel_launch(void* const* d_in, const int* in_sizes, int n_in,
                              void* d_out, int out_size) {
    const int*   inp  = (const int*)  d_in[0];
    const float* h0   = (const float*)d_in[1];
    const float* c0   = (const float*)d_in[2];
    const float* emb  = (const float*)d_in[3];
    const float *W_mx = (const float*)d_in[4],  *b_mx = (const float*)d_in[5];
    const float *W_mh = (const float*)d_in[6],  *b_mh = (const float*)d_in[7];
    const float *W_fx = (const float*)d_in[8],  *b_fx = (const float*)d_in[9];
    const float *W_fm = (const float*)d_in[10], *b_fm = (const float*)d_in[11];
    const float *W_ix = (const float*)d_in[12], *b_ix = (const float*)d_in[13];
    const float *W_im = (const float*)d_in[14], *b_im = (const float*)d_in[15];
    const float *W_ox = (const float*)d_in[16], *b_ox = (const float*)d_in[17];
    const float *W_om = (const float*)d_in[18], *b_om = (const float*)d_in[19];
    const float *W_cx = (const float*)d_in[20], *b_cx = (const float*)d_in[21];
    const float *W_cm = (const float*)d_in[22], *b_cm = (const float*)d_in[23];
    const float *W_dec= (const float*)d_in[24], *b_dec= (const float*)d_in[25];
    float* out = (float*)d_out;

    __nv_bfloat16 *wbf, *h0b;
    uint8_t *w8;
    cudaGetSymbolAddress((void**)&wbf, g_wbf);
    cudaGetSymbolAddress((void**)&h0b, g_h0b);
    cudaGetSymbolAddress((void**)&w8,  g_w8);

    // Fork a secondary stream for off-critical-path weight conversions.
    // Created fresh per call and intentionally not destroyed (kernel_launch is
    // invoked O(1) times; no device memory involved).
    cudaStream_t s1;
    cudaStreamCreateWithFlags(&s1, cudaStreamNonBlocking);
    cudaEvent_t ev0, ev1;
    cudaEventCreateWithFlags(&ev0, cudaEventDisableTiming);
    cudaEventCreateWithFlags(&ev1, cudaEventDisableTiming);

    cudaEventRecord(ev0, 0);
    cudaStreamWaitEvent(s1, ev0, 0);

    // s1: fp8 gate weights + bf16 c-gate weights (needed only after gemm_mt)
    Cvt6 c6;
    const float* gs[6] = {W_fx, W_fm, W_ix, W_im, W_ox, W_om};
    for (int z = 0; z < 3; z++) {
        c6.s[2*z]   = gs[2*z];   c6.d[2*z]   = w8 + OFF8_ZX(z); c6.n4[2*z]   = 2 * MEG / 4;
        c6.s[2*z+1] = gs[2*z+1]; c6.d[2*z+1] = w8 + OFF8_ZM(z); c6.n4[2*z+1] = 4 * MEG / 4;
    }
    cvt_fp8_6<<<dim3(592, 6), 512, 0, s1>>>(c6);

    Cvt2 c2;
    c2.s[0] = W_cx; c2.d[0] = wbf + OFF_CX; c2.n4[0] = 2 * MEG / 4;
    c2.s[1] = W_cm; c2.d[1] = wbf + OFF_CM; c2.n4[1] = 4 * MEG / 4;
    cvt_bf16_2<<<dim3(592, 2), 512, 0, s1>>>(c2);
    cudaEventRecord(ev1, s1);

    // main stream: critical path
    Cvt3 c3;
    c3.s[0] = W_mx; c3.d[0] = wbf + OFF_MX; c3.n4[0] = 2 * MEG / 4;
    c3.s[1] = W_mh; c3.d[1] = wbf + OFF_MH; c3.n4[1] = 4 * MEG / 4;
    c3.s[2] = h0;   c3.d[2] = h0b;          c3.n4[2] = 16 * MEG / 4;
    cvt_bf16_3<<<dim3(592, 3), 512>>>(c3);

    gather_x<<<B_, 256>>>(inp, emb);

    cudaFuncSetAttribute(gemm_mt, cudaFuncAttributeMaxDynamicSharedMemorySize, BF_SMEM);
    gemm_mt<<<dim3(H_ / 128, B_ / 128), 512, BF_SMEM>>>(b_mx, b_mh);

    // join: gate/c weights must be converted before the remaining GEMMs
    cudaStreamWaitEvent(0, ev1, 0);

    cudaFuncSetAttribute(gemm_c, cudaFuncAttributeMaxDynamicSharedMemorySize, BF_SMEM);
    gemm_c<<<dim3(H_ / 128, B_ / 128), 512, BF_SMEM>>>(b_cx, b_cm);

    cudaFuncSetAttribute(gemm_o, cudaFuncAttributeMaxDynamicSharedMemorySize, O_SMEM);
    gemm_o<<<dim3(H_ / 128, B_ / 128), 512, O_SMEM>>>(b_ox, b_om);

    float* hx_out = out + 2 * (size_t)B_;
    float* cx_out = hx_out + (size_t)B_ * H_;
    cudaFuncSetAttribute(gemm_fi, cudaFuncAttributeMaxDynamicSharedMemorySize, FI_SMEM);
    gemm_fi<<<dim3(H_ / 128, B_ / 128), 512, FI_SMEM>>>(
        b_fx, b_fm, b_ix, b_im, c0, hx_out, cx_out);

    decoder<<<(B_ * 32) / 256, 256>>>(hx_out, W_dec, b_dec, out);
}

// round 17
// speedup vs baseline: 1.5203x; 1.5203x over previous
#include <cuda_runtime.h>
#include <cuda_bf16.h>
#include <cuda_fp8.h>
#include <cstdint>

// ---------------------------------------------------------------------------
// mLSTM single step, B=8192, V=50257, E=1024, H=2048, O=2
//   x   = emb[inp]
//   m_t = (x@W_mx^T + b_mx) * (h0@W_mh^T + b_mh)            [bf16 HMMA]
//   ct  = tanh(x@W_cx^T + m_t@W_cm^T + b)                   [bf16 HMMA] -> bf16
//   z_o = x@W_ox^T + m_t@W_om^T + b                         [fp8 QMMA] -> bf16
//   f,i = sigmoid(x@W_zx^T + m_t@W_zm^T + b)                [fp8 QMMA]
//   cx  = f*c0 + i*ct ; hx = sigmoid(z_o)*tanh(cx) ; out = hx@W_dec^T + b_dec
// d_out: [ out(B,2) | hx(B,H) | cx(B,H) ]  fp32
//
// EXACT r10 structure (best measured: 1907.6us) with ONE change: ct stored
// bf16 (saves ~96MB of traffic). Single stream; launch order cvt5 -> cvt6 ->
// gather -> mt -> c -> o -> fi -> decoder.
// All GEMMs: BM=128, BN=128 (fi: 2 gates), 512 thr, warp tile 32x32, 3-stage
// cp.async, one __syncthreads per k-tile, 144B row stride. fp8 scales: x*64,
// W*64, m_t*256; x-phase acc*4 at boundary; dequant 2^-14.
// ---------------------------------------------------------------------------

#define B_  8192
#define E_  1024
#define H_  2048
#define MEG (1 << 20)

__device__ __align__(16) __nv_bfloat16 g_xb [(size_t)B_ * E_];   // bf16 x
__device__ __align__(16) __nv_bfloat16 g_h0b[(size_t)B_ * H_];   // bf16 h0
__device__ __align__(16) __nv_bfloat16 g_mtb[(size_t)B_ * H_];   // bf16 m_t
__device__ __align__(16) __nv_bfloat16 g_zo [(size_t)B_ * H_];   // bf16 z_o pre-act
__device__ __align__(16) __nv_bfloat16 g_ct [(size_t)B_ * H_];   // bf16 c~
__device__ __align__(16) __nv_bfloat16 g_wbf[(size_t)12 * MEG];  // bf16 W_mx,W_mh,W_cx,W_cm
__device__ __align__(16) uint8_t       g_x8 [(size_t)B_ * E_];   // fp8 x*64
__device__ __align__(16) uint8_t       g_mt8[(size_t)B_ * H_];   // fp8 m_t*256
__device__ __align__(16) uint8_t       g_w8 [(size_t)18 * MEG];  // fp8 f,i,o W*64

#define OFF_MX 0
#define OFF_MH (2 * MEG)
#define OFF_CX (6 * MEG)
#define OFF_CM (8 * MEG)
#define OFF8_ZX(z) ((size_t)(z) * 6 * MEG)            // z: 0=f 1=i 2=o
#define OFF8_ZM(z) ((size_t)(z) * 6 * MEG + 2 * MEG)

// ---------------------------------------------------------------------------
// helpers
// ---------------------------------------------------------------------------
__device__ __forceinline__ uint32_t smem_u32(const void* p) {
    uint32_t a;
    asm("{ .reg .u64 t; cvta.to.shared.u64 t, %1; cvt.u32.u64 %0, t; }"
        : "=r"(a) : "l"(p));
    return a;
}
__device__ __forceinline__ void cpa16(uint32_t dst, const void* src) {
    asm volatile("cp.async.cg.shared.global [%0], [%1], 16;\n" :: "r"(dst), "l"(src));
}
__device__ __forceinline__ void cp_commit() { asm volatile("cp.async.commit_group;\n" ::); }
template <int N> __device__ __forceinline__ void cp_wait() {
    asm volatile("cp.async.wait_group %0;\n" :: "n"(N));
}
__device__ __forceinline__ void ldsm4(uint32_t& r0, uint32_t& r1, uint32_t& r2,
                                      uint32_t& r3, uint32_t addr) {
    asm volatile("ldmatrix.sync.aligned.m8n8.x4.shared.b16 {%0,%1,%2,%3}, [%4];"
                 : "=r"(r0), "=r"(r1), "=r"(r2), "=r"(r3) : "r"(addr));
}
__device__ __forceinline__ void mma16816(float c[4], const uint32_t a[4], const uint32_t b[2]) {
    asm volatile(
        "mma.sync.aligned.m16n8k16.row.col.f32.bf16.bf16.f32 "
        "{%0,%1,%2,%3}, {%4,%5,%6,%7}, {%8,%9}, {%0,%1,%2,%3};\n"
        : "+f"(c[0]), "+f"(c[1]), "+f"(c[2]), "+f"(c[3])
        : "r"(a[0]), "r"(a[1]), "r"(a[2]), "r"(a[3]), "r"(b[0]), "r"(b[1]));
}
__device__ __forceinline__ void mma_fp8(float c[4], const uint32_t a[4], const uint32_t b[2]) {
    asm volatile(
        "mma.sync.aligned.m16n8k32.row.col.f32.e4m3.e4m3.f32 "
        "{%0,%1,%2,%3}, {%4,%5,%6,%7}, {%8,%9}, {%0,%1,%2,%3};\n"
        : "+f"(c[0]), "+f"(c[1]), "+f"(c[2]), "+f"(c[3])
        : "r"(a[0]), "r"(a[1]), "r"(a[2]), "r"(a[3]), "r"(b[0]), "r"(b[1]));
}
__device__ __forceinline__ uint16_t fp8pair(float v0, float v1) {
    uint16_t r;
    asm("cvt.rn.satfinite.e4m3x2.f32 %0, %1, %2;" : "=h"(r) : "f"(v1), "f"(v0));
    return r;
}
__device__ __forceinline__ float sigf(float v)   { return 1.f / (1.f + __expf(-v)); }
__device__ __forceinline__ float tanhf_(float v) { return fmaf(2.f, 1.f / (1.f + __expf(-2.f * v)), -1.f); }

// ---------------------------------------------------------------------------
// conversions + gather (r10 configs)
// ---------------------------------------------------------------------------
struct Cvt5 { const float* s[5]; __nv_bfloat16* d[5]; int n4[5]; };

__global__ void cvt_f32_bf16(Cvt5 a) {
    const int seg = blockIdx.y;
    const float4* __restrict__ s = (const float4*)a.s[seg];
    uint2* __restrict__ d = (uint2*)a.d[seg];
    const int n4 = a.n4[seg];
    for (int i = blockIdx.x * blockDim.x + threadIdx.x; i < n4;
         i += gridDim.x * blockDim.x) {
        float4 v = s[i];
        __nv_bfloat162 lo = __float22bfloat162_rn(make_float2(v.x, v.y));
        __nv_bfloat162 hi = __float22bfloat162_rn(make_float2(v.z, v.w));
        uint2 o; o.x = *(unsigned*)&lo; o.y = *(unsigned*)&hi;
        d[i] = o;
    }
}

struct Cvt6 { const float* s[6]; uint8_t* d[6]; int n4[6]; };

__global__ void cvt_f32_fp8(Cvt6 a) {
    const int seg = blockIdx.y;
    const float4* __restrict__ s = (const float4*)a.s[seg];
    uint32_t* __restrict__ d = (uint32_t*)a.d[seg];
    const int n4 = a.n4[seg];
    for (int i = blockIdx.x * blockDim.x + threadIdx.x; i < n4;
         i += gridDim.x * blockDim.x) {
        float4 v = s[i];
        uint32_t lo = fp8pair(v.x * 64.f, v.y * 64.f);
        uint32_t hi = fp8pair(v.z * 64.f, v.w * 64.f);
        d[i] = lo | (hi << 16);
    }
}

__global__ void gather_x(const int* __restrict__ inp, const float* __restrict__ emb) {
    const int b = blockIdx.x;
    const int v = inp[b];
    float4 t = ((const float4*)(emb + (size_t)v * E_))[threadIdx.x];
    __nv_bfloat162 lo = __float22bfloat162_rn(make_float2(t.x, t.y));
    __nv_bfloat162 hi = __float22bfloat162_rn(make_float2(t.z, t.w));
    uint2 o; o.x = *(unsigned*)&lo; o.y = *(unsigned*)&hi;
    ((uint2*)(g_xb + (size_t)b * E_))[threadIdx.x] = o;
    uint32_t l8 = fp8pair(t.x * 64.f, t.y * 64.f);
    uint32_t h8 = fp8pair(t.z * 64.f, t.w * 64.f);
    ((uint32_t*)(g_x8 + (size_t)b * E_))[threadIdx.x] = l8 | (h8 << 16);
}

// ---------------------------------------------------------------------------
// bf16 GEMMs: BM=128, BN=128, BK=64; rows 144 B; 3 stages; one sync/iter
// ---------------------------------------------------------------------------
#define BST    18432                 // 128 rows * 144 B
#define STG_B  (2 * BST)
#define BF_SMEM (3 * STG_B + 1024)
#define NTB_X  16
#define NTB    48

// m_t: dual accumulation -> bf16 + fp8*256
__global__ __launch_bounds__(512, 1)
void gemm_mt(const float* __restrict__ b_mx, const float* __restrict__ b_mh) {
    extern __shared__ __align__(16) char sm[];
    const uint32_t smb = smem_u32(sm);
    float* bs = (float*)(sm + 3 * STG_B);

    const int m0 = blockIdx.y * 128;
    const int n0 = blockIdx.x * 128;
    const int tid = threadIdx.x, lane = tid & 31, warp = tid >> 5;
    const int wm = warp & 3, wn = warp >> 2;
    const int g = lane >> 2, ti = lane & 3;
    const int l16 = lane & 15, kh = lane >> 4;

    if (tid < 128) {
        bs[tid]       = b_mx[n0 + tid];
        bs[128 + tid] = b_mh[n0 + tid];
    }

    float ax[2][4][4], ah[2][4][4];
#pragma unroll
    for (int mt = 0; mt < 2; mt++)
#pragma unroll
        for (int q = 0; q < 4; q++)
#pragma unroll
            for (int j = 0; j < 4; j++) { ax[mt][q][j] = 0.f; ah[mt][q][j] = 0.f; }

    auto issue = [&](int t, int s) {
        const __nv_bfloat16 *Ab, *Wb; int ld; int tt = t;
        if (t < NTB_X) { Ab = g_xb;  Wb = g_wbf + OFF_MX; ld = E_; }
        else           { Ab = g_h0b; Wb = g_wbf + OFF_MH; ld = H_; tt = t - NTB_X; }
        const int k0 = tt * 64;
        const uint32_t base = smb + s * STG_B;
#pragma unroll
        for (int i = 0; i < 2; i++) {
            int lin = tid + i * 512, r = lin >> 3, c = lin & 7;
            cpa16(base + r * 144 + c * 16,       Ab + (size_t)(m0 + r) * ld + k0 + c * 8);
            cpa16(base + BST + r * 144 + c * 16, Wb + (size_t)(n0 + r) * ld + k0 + c * 8);
        }
        cp_commit();
    };

    issue(0, 0); issue(1, 1);
    for (int t = 0; t < NTB; t++) {
        if (t + 1 < NTB) cp_wait<1>(); else cp_wait<0>();
        __syncthreads();
        if (t + 2 < NTB) issue(t + 2, (t + 2) % 3);
        const uint32_t base = smb + (t % 3) * STG_B;
        const bool px = (t < NTB_X);
#pragma unroll
        for (int ks = 0; ks < 4; ks++) {
            const int kb = ks * 32;
            uint32_t af[2][4];
#pragma unroll
            for (int mt = 0; mt < 2; mt++)
                ldsm4(af[mt][0], af[mt][1], af[mt][2], af[mt][3],
                      base + (wm * 32 + mt * 16 + l16) * 144 + kb + kh * 16);
#pragma unroll
            for (int nt = 0; nt < 2; nt++) {
                uint32_t r0, r1, r2, r3;
                ldsm4(r0, r1, r2, r3,
                      base + BST + (wn * 32 + nt * 16 + l16) * 144 + kb + kh * 16);
                uint32_t b0[2] = {r0, r2}, b1[2] = {r1, r3};
                if (px) {
#pragma unroll
                    for (int mt = 0; mt < 2; mt++) {
                        mma16816(ax[mt][nt * 2],     af[mt], b0);
                        mma16816(ax[mt][nt * 2 + 1], af[mt], b1);
                    }
                } else {
#pragma unroll
                    for (int mt = 0; mt < 2; mt++) {
                        mma16816(ah[mt][nt * 2],     af[mt], b0);
                        mma16816(ah[mt][nt * 2 + 1], af[mt], b1);
                    }
                }
            }
        }
    }

#pragma unroll
    for (int mt = 0; mt < 2; mt++)
#pragma unroll
        for (int q = 0; q < 4; q++) {
            const int nl = wn * 32 + q * 8 + ti * 2;
            const int n = n0 + nl;
#pragma unroll
            for (int h = 0; h < 2; h++) {
                const int m = m0 + wm * 32 + mt * 16 + g + h * 8;
                float v0 = (ax[mt][q][h * 2 + 0] + bs[nl + 0]) *
                           (ah[mt][q][h * 2 + 0] + bs[128 + nl + 0]);
                float v1 = (ax[mt][q][h * 2 + 1] + bs[nl + 1]) *
                           (ah[mt][q][h * 2 + 1] + bs[128 + nl + 1]);
                __nv_bfloat162 p = __float22bfloat162_rn(make_float2(v0, v1));
                *(unsigned*)(g_mtb + (size_t)m * H_ + n) = *(unsigned*)&p;
                *(uint16_t*)(g_mt8 + (size_t)m * H_ + n) =
                    fp8pair(v0 * 256.f, v1 * 256.f);
            }
        }
}

// c-gate: ct = tanh(x@Wcx + m_t@Wcm + b) -> bf16
__global__ __launch_bounds__(512, 1)
void gemm_c(const float* __restrict__ bcx, const float* __restrict__ bcm) {
    extern __shared__ __align__(16) char sm[];
    const uint32_t smb = smem_u32(sm);
    float* bs = (float*)(sm + 3 * STG_B);

    const int m0 = blockIdx.y * 128;
    const int n0 = blockIdx.x * 128;
    const int tid = threadIdx.x, lane = tid & 31, warp = tid >> 5;
    const int wm = warp & 3, wn = warp >> 2;
    const int g = lane >> 2, ti = lane & 3;
    const int l16 = lane & 15, kh = lane >> 4;

    if (tid < 128) bs[tid] = bcx[n0 + tid] + bcm[n0 + tid];

    float acc[2][4][4];
#pragma unroll
    for (int mt = 0; mt < 2; mt++)
#pragma unroll
        for (int q = 0; q < 4; q++)
#pragma unroll
            for (int j = 0; j < 4; j++) acc[mt][q][j] = 0.f;

    auto issue = [&](int t, int s) {
        const __nv_bfloat16 *Ab, *Wb; int ld; int tt = t;
        if (t < NTB_X) { Ab = g_xb;  Wb = g_wbf + OFF_CX; ld = E_; }
        else           { Ab = g_mtb; Wb = g_wbf + OFF_CM; ld = H_; tt = t - NTB_X; }
        const int k0 = tt * 64;
        const uint32_t base = smb + s * STG_B;
#pragma unroll
        for (int i = 0; i < 2; i++) {
            int lin = tid + i * 512, r = lin >> 3, c = lin & 7;
            cpa16(base + r * 144 + c * 16,       Ab + (size_t)(m0 + r) * ld + k0 + c * 8);
            cpa16(base + BST + r * 144 + c * 16, Wb + (size_t)(n0 + r) * ld + k0 + c * 8);
        }
        cp_commit();
    };

    issue(0, 0); issue(1, 1);
    for (int t = 0; t < NTB; t++) {
        if (t + 1 < NTB) cp_wait<1>(); else cp_wait<0>();
        __syncthreads();
        if (t + 2 < NTB) issue(t + 2, (t + 2) % 3);
        const uint32_t base = smb + (t % 3) * STG_B;
#pragma unroll
        for (int ks = 0; ks < 4; ks++) {
            const int kb = ks * 32;
            uint32_t af[2][4];
#pragma unroll
            for (int mt = 0; mt < 2; mt++)
                ldsm4(af[mt][0], af[mt][1], af[mt][2], af[mt][3],
                      base + (wm * 32 + mt * 16 + l16) * 144 + kb + kh * 16);
#pragma unroll
            for (int nt = 0; nt < 2; nt++) {
                uint32_t r0, r1, r2, r3;
                ldsm4(r0, r1, r2, r3,
                      base + BST + (wn * 32 + nt * 16 + l16) * 144 + kb + kh * 16);
                uint32_t b0[2] = {r0, r2}, b1[2] = {r1, r3};
#pragma unroll
                for (int mt = 0; mt < 2; mt++) {
                    mma16816(acc[mt][nt * 2],     af[mt], b0);
                    mma16816(acc[mt][nt * 2 + 1], af[mt], b1);
                }
            }
        }
    }

#pragma unroll
    for (int mt = 0; mt < 2; mt++)
#pragma unroll
        for (int q = 0; q < 4; q++) {
            const int nl = wn * 32 + q * 8 + ti * 2;
            const int n = n0 + nl;
#pragma unroll
            for (int h = 0; h < 2; h++) {
                const int m = m0 + wm * 32 + mt * 16 + g + h * 8;
                float v0 = tanhf_(acc[mt][q][h * 2 + 0] + bs[nl + 0]);
                float v1 = tanhf_(acc[mt][q][h * 2 + 1] + bs[nl + 1]);
                __nv_bfloat162 p = __float22bfloat162_rn(make_float2(v0, v1));
                *(unsigned*)(g_ct + (size_t)m * H_ + n) = *(unsigned*)&p;
            }
        }
}

// ---------------------------------------------------------------------------
// fp8 GEMMs: BM=128, BN=128, BK=128 B; rows 144 B; 3 stages; one sync/iter
// ---------------------------------------------------------------------------
#define F8_NT  24
#define F8_NX  8
#define DQ_    (1.f / 16384.f)
#define O_STG  (2 * BST)
#define O_SMEM (3 * O_STG + 1024)

// o-gate: z_o = x@Wox + m_t@Wom + b  -> bf16 pre-act
__global__ __launch_bounds__(512, 1)
void gemm_o(const float* __restrict__ box_, const float* __restrict__ bom) {
    extern __shared__ __align__(16) char sm[];
    const uint32_t smb = smem_u32(sm);
    float* bs = (float*)(sm + 3 * O_STG);

    const int m0 = blockIdx.y * 128;
    const int n0 = blockIdx.x * 128;
    const int tid = threadIdx.x, lane = tid & 31, warp = tid >> 5;
    const int wm = warp & 3, wn = warp >> 2;
    const int g = lane >> 2, ti = lane & 3;
    const int l16 = lane & 15, kh = lane >> 4;

    if (tid < 128) bs[tid] = box_[n0 + tid] + bom[n0 + tid];

    float acc[2][4][4];
#pragma unroll
    for (int mt = 0; mt < 2; mt++)
#pragma unroll
        for (int q = 0; q < 4; q++)
#pragma unroll
            for (int j = 0; j < 4; j++) acc[mt][q][j] = 0.f;

    auto issue = [&](int t, int s) {
        const bool xph = (t < F8_NX);
        const uint8_t* Ab = xph ? g_x8 : g_mt8;
        const uint8_t* Wb = g_w8 + (xph ? OFF8_ZX(2) : OFF8_ZM(2));
        const int ld = xph ? E_ : H_;
        const int k0 = (xph ? t : t - F8_NX) * 128;
        const uint32_t base = smb + s * O_STG;
#pragma unroll
        for (int i = 0; i < 2; i++) {
            int lin = tid + i * 512, r = lin >> 3, c = lin & 7;
            cpa16(base + r * 144 + c * 16,       Ab + (size_t)(m0 + r) * ld + k0 + c * 16);
            cpa16(base + BST + r * 144 + c * 16, Wb + (size_t)(n0 + r) * ld + k0 + c * 16);
        }
        cp_commit();
    };

    issue(0, 0); issue(1, 1);
    for (int t = 0; t < F8_NT; t++) {
        if (t + 1 < F8_NT) cp_wait<1>(); else cp_wait<0>();
        __syncthreads();
        if (t + 2 < F8_NT) issue(t + 2, (t + 2) % 3);
        if (t == F8_NX) {
#pragma unroll
            for (int mt = 0; mt < 2; mt++)
#pragma unroll
                for (int q = 0; q < 4; q++)
#pragma unroll
                    for (int j = 0; j < 4; j++) acc[mt][q][j] *= 4.f;
        }
        const uint32_t base = smb + (t % 3) * O_STG;
#pragma unroll
        for (int ks = 0; ks < 4; ks++) {
            const int kb = ks * 32;
            uint32_t af[2][4];
#pragma unroll
            for (int mt = 0; mt < 2; mt++)
                ldsm4(af[mt][0], af[mt][1], af[mt][2], af[mt][3],
                      base + (wm * 32 + mt * 16 + l16) * 144 + kb + kh * 16);
#pragma unroll
            for (int nt = 0; nt < 2; nt++) {
                uint32_t r0, r1, r2, r3;
                ldsm4(r0, r1, r2, r3,
                      base + BST + (wn * 32 + nt * 16 + l16) * 144 + kb + kh * 16);
                uint32_t b0[2] = {r0, r2}, b1[2] = {r1, r3};
#pragma unroll
                for (int mt = 0; mt < 2; mt++) {
                    mma_fp8(acc[mt][nt * 2],     af[mt], b0);
                    mma_fp8(acc[mt][nt * 2 + 1], af[mt], b1);
                }
            }
        }
    }

#pragma unroll
    for (int mt = 0; mt < 2; mt++)
#pragma unroll
        for (int q = 0; q < 4; q++) {
            const int nl = wn * 32 + q * 8 + ti * 2;
            const int n = n0 + nl;
#pragma unroll
            for (int h = 0; h < 2; h++) {
                const int m = m0 + wm * 32 + mt * 16 + g + h * 8;
                float v0 = acc[mt][q][h * 2 + 0] * DQ_ + bs[nl + 0];
                float v1 = acc[mt][q][h * 2 + 1] * DQ_ + bs[nl + 1];
                __nv_bfloat162 p = __float22bfloat162_rn(make_float2(v0, v1));
                *(unsigned*)(g_zo + (size_t)m * H_ + n) = *(unsigned*)&p;
            }
        }
}

// f,i gates + final combine: cx/hx into d_out
#define FI_STG (3 * BST)                 // A + 2 B tiles
#define FI_SMEM (3 * FI_STG + 1024)

__global__ __launch_bounds__(512, 1)
void gemm_fi(const float* __restrict__ bfx, const float* __restrict__ bfm,
             const float* __restrict__ bix, const float* __restrict__ bim,
             const float* __restrict__ c0,
             float* __restrict__ hx, float* __restrict__ cx) {
    extern __shared__ __align__(16) char sm[];
    const uint32_t smb = smem_u32(sm);
    float* bs = (float*)(sm + 3 * FI_STG);

    const int m0 = blockIdx.y * 128;
    const int n0 = blockIdx.x * 128;
    const int tid = threadIdx.x, lane = tid & 31, warp = tid >> 5;
    const int wm = warp & 3, wn = warp >> 2;
    const int g = lane >> 2, ti = lane & 3;
    const int l16 = lane & 15, kh = lane >> 4;

    if (tid < 128) {
        const int n = n0 + tid;
        bs[tid]       = bfx[n] + bfm[n];
        bs[128 + tid] = bix[n] + bim[n];
    }

    float acc[2][2][4][4];   // [z][mt][q][j]
#pragma unroll
    for (int z = 0; z < 2; z++)
#pragma unroll
        for (int mt = 0; mt < 2; mt++)
#pragma unroll
            for (int q = 0; q < 4; q++)
#pragma unroll
                for (int j = 0; j < 4; j++) acc[z][mt][q][j] = 0.f;

    auto issue = [&](int t, int s) {
        const bool xph = (t < F8_NX);
        const uint8_t* Ab = xph ? g_x8 : g_mt8;
        const int ld = xph ? E_ : H_;
        const int k0 = (xph ? t : t - F8_NX) * 128;
        const uint32_t base = smb + s * FI_STG;
#pragma unroll
        for (int i = 0; i < 2; i++) {
            int lin = tid + i * 512, r = lin >> 3, c = lin & 7;
            cpa16(base + r * 144 + c * 16, Ab + (size_t)(m0 + r) * ld + k0 + c * 16);
        }
#pragma unroll
        for (int i = 0; i < 4; i++) {
            int lin = tid + i * 512;
            int z = lin >> 10, rr = (lin >> 3) & 127, cc = lin & 7;
            const uint8_t* Wb = g_w8 + (xph ? OFF8_ZX(z) : OFF8_ZM(z));
            cpa16(base + BST + z * BST + rr * 144 + cc * 16,
                  Wb + (size_t)(n0 + rr) * ld + k0 + cc * 16);
        }
        cp_commit();
    };

    issue(0, 0); issue(1, 1);
    for (int t = 0; t < F8_NT; t++) {
        if (t + 1 < F8_NT) cp_wait<1>(); else cp_wait<0>();
        __syncthreads();
        if (t + 2 < F8_NT) issue(t + 2, (t + 2) % 3);
        if (t == F8_NX) {
#pragma unroll
            for (int z = 0; z < 2; z++)
#pragma unroll
                for (int mt = 0; mt < 2; mt++)
#pragma unroll
                    for (int q = 0; q < 4; q++)
#pragma unroll
                        for (int j = 0; j < 4; j++) acc[z][mt][q][j] *= 4.f;
        }
        const uint32_t base = smb + (t % 3) * FI_STG;
#pragma unroll
        for (int ks = 0; ks < 4; ks++) {
            const int kb = ks * 32;
            uint32_t af[2][4];
#pragma unroll
            for (int mt = 0; mt < 2; mt++)
                ldsm4(af[mt][0], af[mt][1], af[mt][2], af[mt][3],
                      base + (wm * 32 + mt * 16 + l16) * 144 + kb + kh * 16);
#pragma unroll
            for (int z = 0; z < 2; z++)
#pragma unroll
                for (int nt = 0; nt < 2; nt++) {
                    uint32_t r0, r1, r2, r3;
                    ldsm4(r0, r1, r2, r3,
                          base + BST + z * BST + (wn * 32 + nt * 16 + l16) * 144 + kb + kh * 16);
                    uint32_t b0[2] = {r0, r2}, b1[2] = {r1, r3};
#pragma unroll
                    for (int mt = 0; mt < 2; mt++) {
                        mma_fp8(acc[z][mt][nt * 2],     af[mt], b0);
                        mma_fp8(acc[z][mt][nt * 2 + 1], af[mt], b1);
                    }
                }
        }
    }

    // epilogue: f,i sigmoids + o (z_o) + ct (bf16) + c0 -> cx, hx
#pragma unroll
    for (int mt = 0; mt < 2; mt++)
#pragma unroll
        for (int q = 0; q < 4; q++) {
            const int nl = wn * 32 + q * 8 + ti * 2;
            const int n = n0 + nl;
#pragma unroll
            for (int h = 0; h < 2; h++) {
                const int m = m0 + wm * 32 + mt * 16 + g + h * 8;
                const size_t off = (size_t)m * H_ + n;
                float2 c0v = *(const float2*)(c0 + off);
                unsigned ctb = *(const unsigned*)(g_ct + off);
                unsigned zob = *(const unsigned*)(g_zo + off);
                __nv_bfloat162 ct2 = *(__nv_bfloat162*)&ctb;
                __nv_bfloat162 zo2 = *(__nv_bfloat162*)&zob;
                float2 hv, cvv;
#pragma unroll
                for (int j = 0; j < 2; j++) {
                    const int e = h * 2 + j;
                    float fg = sigf(acc[0][mt][q][e] * DQ_ + bs[nl + j]);
                    float ig = sigf(acc[1][mt][q][e] * DQ_ + bs[128 + nl + j]);
                    float og = sigf(j ? __bfloat162float(zo2.y)
                                      : __bfloat162float(zo2.x));
                    float ct  = j ? __bfloat162float(ct2.y) : __bfloat162float(ct2.x);
                    float c0e = j ? c0v.y : c0v.x;
                    float cv = fg * c0e + ig * ct;
                    ((float*)&cvv)[j] = cv;
                    ((float*)&hv)[j]  = og * tanhf_(cv);
                }
                *(float2*)(cx + off) = cvv;
                *(float2*)(hx + off) = hv;
            }
        }
}

// ---------------------------------------------------------------------------
// decoder
// ---------------------------------------------------------------------------
__global__ void decoder(const float* __restrict__ hx, const float* __restrict__ Wd,
                        const float* __restrict__ bd, float* __restrict__ out) {
    const int gw = (blockIdx.x * blockDim.x + threadIdx.x) >> 5;
    const int lane = threadIdx.x & 31;
    if (gw >= B_) return;
    const float4* h4 = (const float4*)(hx + (size_t)gw * H_);
    const float4* w0 = (const float4*)(Wd);
    const float4* w1 = (const float4*)(Wd + H_);
    float s0 = 0.f, s1 = 0.f;
    for (int i = lane; i < H_ / 4; i += 32) {
        float4 h = h4[i], a = w0[i], b = w1[i];
        s0 += h.x * a.x + h.y * a.y + h.z * a.z + h.w * a.w;
        s1 += h.x * b.x + h.y * b.y + h.z * b.z + h.w * b.w;
    }
#pragma unroll
    for (int o = 16; o; o >>= 1) {
        s0 += __shfl_xor_sync(0xFFFFFFFFu, s0, o);
        s1 += __shfl_xor_sync(0xFFFFFFFFu, s1, o);
    }
    if (lane == 0) {
        out[(size_t)gw * 2 + 0] = s0 + bd[0];
        out[(size_t)gw * 2 + 1] = s1 + bd[1];
    }
}

// ---------------------------------------------------------------------------
extern "C" void kernel_launch(void* const* d_in, const int* in_sizes, int n_in,
                              void* d_out, int out_size) {
    const int*   inp  = (const int*)  d_in[0];
    const float* h0   = (const float*)d_in[1];
    const float* c0   = (const float*)d_in[2];
    const float* emb  = (const float*)d_in[3];
    const float *W_mx = (const float*)d_in[4],  *b_mx = (const float*)d_in[5];
    const float *W_mh = (const float*)d_in[6],  *b_mh = (const float*)d_in[7];
    const float *W_fx = (const float*)d_in[8],  *b_fx = (const float*)d_in[9];
    const float *W_fm = (const float*)d_in[10], *b_fm = (const float*)d_in[11];
    const float *W_ix = (const float*)d_in[12], *b_ix = (const float*)d_in[13];
    const float *W_im = (const float*)d_in[14], *b_im = (const float*)d_in[15];
    const float *W_ox = (const float*)d_in[16], *b_ox = (const float*)d_in[17];
    const float *W_om = (const float*)d_in[18], *b_om = (const float*)d_in[19];
    const float *W_cx = (const float*)d_in[20], *b_cx = (const float*)d_in[21];
    const float *W_cm = (const float*)d_in[22], *b_cm = (const float*)d_in[23];
    const float *W_dec= (const float*)d_in[24], *b_dec= (const float*)d_in[25];
    float* out = (float*)d_out;

    __nv_bfloat16 *wbf, *h0b;
    uint8_t *w8;
    cudaGetSymbolAddress((void**)&wbf, g_wbf);
    cudaGetSymbolAddress((void**)&h0b, g_h0b);
    cudaGetSymbolAddress((void**)&w8,  g_w8);

    // 1) bf16 conversions (r10 config)
    Cvt5 c5;
    c5.s[0] = W_mx; c5.d[0] = wbf + OFF_MX; c5.n4[0] = 2 * MEG / 4;
    c5.s[1] = W_mh; c5.d[1] = wbf + OFF_MH; c5.n4[1] = 4 * MEG / 4;
    c5.s[2] = W_cx; c5.d[2] = wbf + OFF_CX; c5.n4[2] = 2 * MEG / 4;
    c5.s[3] = W_cm; c5.d[3] = wbf + OFF_CM; c5.n4[3] = 4 * MEG / 4;
    c5.s[4] = h0;   c5.d[4] = h0b;          c5.n4[4] = 16 * MEG / 4;
    cvt_f32_bf16<<<dim3(1024, 5), 256>>>(c5);

    // 2) fp8 conversions (f=0, i=1, o=2)
    Cvt6 c6;
    const float* gs[6] = {W_fx, W_fm, W_ix, W_im, W_ox, W_om};
    for (int z = 0; z < 3; z++) {
        c6.s[2*z]   = gs[2*z];   c6.d[2*z]   = w8 + OFF8_ZX(z); c6.n4[2*z]   = 2 * MEG / 4;
        c6.s[2*z+1] = gs[2*z+1]; c6.d[2*z+1] = w8 + OFF8_ZM(z); c6.n4[2*z+1] = 4 * MEG / 4;
    }
    cvt_f32_fp8<<<dim3(1024, 6), 256>>>(c6);

    // 3) gather
    gather_x<<<B_, 256>>>(inp, emb);

    // 4) m_t
    cudaFuncSetAttribute(gemm_mt, cudaFuncAttributeMaxDynamicSharedMemorySize, BF_SMEM);
    gemm_mt<<<dim3(H_ / 128, B_ / 128), 512, BF_SMEM>>>(b_mx, b_mh);

    // 5) ct (bf16)
    cudaFuncSetAttribute(gemm_c, cudaFuncAttributeMaxDynamicSharedMemorySize, BF_SMEM);
    gemm_c<<<dim3(H_ / 128, B_ / 128), 512, BF_SMEM>>>(b_cx, b_cm);

    // 6) z_o (fp8)
    cudaFuncSetAttribute(gemm_o, cudaFuncAttributeMaxDynamicSharedMemorySize, O_SMEM);
    gemm_o<<<dim3(H_ / 128, B_ / 128), 512, O_SMEM>>>(b_ox, b_om);

    // 7) f,i (fp8) + final combine into d_out
    float* hx_out = out + 2 * (size_t)B_;
    float* cx_out = hx_out + (size_t)B_ * H_;
    cudaFuncSetAttribute(gemm_fi, cudaFuncAttributeMaxDynamicSharedMemorySize, FI_SMEM);
    gemm_fi<<<dim3(H_ / 128, B_ / 128), 512, FI_SMEM>>>(
        b_fx, b_fm, b_ix, b_im, c0, hx_out, cx_out);

    // 8) decoder
    decoder<<<(B_ * 32) / 256, 256>>>(hx_out, W_dec, b_dec, out);
}